// round 1
// baseline (speedup 1.0000x reference)
#include <cuda_runtime.h>
#include <math.h>

#define NB   8192
#define DIM  2048
#define RANK 512

// Scratch (allocation-free contract: __device__ globals)
__device__ float g_P[2 * NB * RANK];   // projections; normalized in place. rows 0..NB-1 = Zhat, NB.. = Chat
__device__ float g_sumexp[NB];
__device__ float g_diag[NB];
__device__ float g_colz[RANK];
__device__ float g_colc[RANK];

__global__ void init_kernel() {
    int i = blockIdx.x * blockDim.x + threadIdx.x;
    if (i < NB) g_sumexp[i] = 0.f;
    if (i < RANK) { g_colz[i] = 0.f; g_colc[i] = 0.f; }
}

// P[2NB, RANK] = h[2NB, DIM] @ W[RANK, DIM]^T   (both operands K-contiguous)
// BM=BN=128, BK=16, 256 threads, 8x8 register tile
__global__ __launch_bounds__(256) void proj_kernel(const float* __restrict__ h,
                                                   const float* __restrict__ W) {
    __shared__ float As[16][128];
    __shared__ float Bs[16][128];
    const int tid = threadIdx.x;
    const int M0 = blockIdx.y * 128;
    const int N0 = blockIdx.x * 128;
    const int lr = tid >> 2;          // 0..63
    const int lc = (tid & 3) << 2;    // 0,4,8,12
    const int tx = tid & 15, ty = tid >> 4;
    float acc[8][8] = {};

    for (int k0 = 0; k0 < DIM; k0 += 16) {
#pragma unroll
        for (int r = 0; r < 2; ++r) {
            float4 a = *(const float4*)&h[(size_t)(M0 + lr + r * 64) * DIM + k0 + lc];
            As[lc + 0][lr + r * 64] = a.x; As[lc + 1][lr + r * 64] = a.y;
            As[lc + 2][lr + r * 64] = a.z; As[lc + 3][lr + r * 64] = a.w;
            float4 b = *(const float4*)&W[(size_t)(N0 + lr + r * 64) * DIM + k0 + lc];
            Bs[lc + 0][lr + r * 64] = b.x; Bs[lc + 1][lr + r * 64] = b.y;
            Bs[lc + 2][lr + r * 64] = b.z; Bs[lc + 3][lr + r * 64] = b.w;
        }
        __syncthreads();
#pragma unroll
        for (int k = 0; k < 16; ++k) {
            float a[8], b[8];
            *(float4*)&a[0] = *(const float4*)&As[k][ty * 8];
            *(float4*)&a[4] = *(const float4*)&As[k][ty * 8 + 4];
            *(float4*)&b[0] = *(const float4*)&Bs[k][tx * 8];
            *(float4*)&b[4] = *(const float4*)&Bs[k][tx * 8 + 4];
#pragma unroll
            for (int i = 0; i < 8; ++i)
#pragma unroll
                for (int j = 0; j < 8; ++j)
                    acc[i][j] = fmaf(a[i], b[j], acc[i][j]);
        }
        __syncthreads();
    }
#pragma unroll
    for (int i = 0; i < 8; ++i)
#pragma unroll
        for (int j = 0; j < 8; j += 4) {
            float4 v = make_float4(acc[i][j], acc[i][j + 1], acc[i][j + 2], acc[i][j + 3]);
            *(float4*)&g_P[(size_t)(M0 + ty * 8 + i) * RANK + N0 + tx * 8 + j] = v;
        }
}

// normalize each row of g_P to unit L2 norm (eps never binds: ||row|| ~ 20)
__global__ __launch_bounds__(128) void normalize_kernel() {
    const int row = blockIdx.x;       // 0..2NB-1
    const int tid = threadIdx.x;      // 128 threads * 4 floats = 512
    float4 v = *(float4*)&g_P[(size_t)row * RANK + tid * 4];
    float ss = v.x * v.x + v.y * v.y + v.z * v.z + v.w * v.w;
#pragma unroll
    for (int o = 16; o; o >>= 1) ss += __shfl_xor_sync(0xffffffffu, ss, o);
    __shared__ float ws[4];
    if ((tid & 31) == 0) ws[tid >> 5] = ss;
    __syncthreads();
    float inv = rsqrtf(ws[0] + ws[1] + ws[2] + ws[3]);
    v.x *= inv; v.y *= inv; v.z *= inv; v.w *= inv;
    *(float4*)&g_P[(size_t)row * RANK + tid * 4] = v;
}

// diag_i = Zhat[i] . Chat[i]
__global__ __launch_bounds__(128) void diag_kernel() {
    const int i = blockIdx.x;         // 0..NB-1
    const int tid = threadIdx.x;
    float4 z = *(const float4*)&g_P[(size_t)i * RANK + tid * 4];
    float4 c = *(const float4*)&g_P[(size_t)(i + NB) * RANK + tid * 4];
    float d = z.x * c.x + z.y * c.y + z.z * c.z + z.w * c.w;
#pragma unroll
    for (int o = 16; o; o >>= 1) d += __shfl_xor_sync(0xffffffffu, d, o);
    __shared__ float ws[4];
    if ((tid & 31) == 0) ws[tid >> 5] = d;
    __syncthreads();
    if (tid == 0) g_diag[i] = ws[0] + ws[1] + ws[2] + ws[3];
}

// column sums of Zhat and Chat
__global__ __launch_bounds__(256) void colsum_kernel() {
    const int rb = blockIdx.x * 128;  // 64 blocks
    const int t = threadIdx.x;        // 256 threads; cols t and t+256
    float z0 = 0.f, z1 = 0.f, c0 = 0.f, c1 = 0.f;
    for (int r = 0; r < 128; ++r) {
        const float* pz = &g_P[(size_t)(rb + r) * RANK];
        const float* pc = &g_P[(size_t)(rb + r + NB) * RANK];
        z0 += pz[t]; z1 += pz[t + 256];
        c0 += pc[t]; c1 += pc[t + 256];
    }
    atomicAdd(&g_colz[t], z0); atomicAdd(&g_colz[t + 256], z1);
    atomicAdd(&g_colc[t], c0); atomicAdd(&g_colc[t + 256], c1);
}

// sumexp_i = sum_j exp( (Zhat_i . Chat_j) * 10 )  — fused GEMM + exp row-reduce
__global__ __launch_bounds__(256) void sim_kernel() {
    const float* __restrict__ A = g_P;
    const float* __restrict__ Bm = g_P + (size_t)NB * RANK;
    __shared__ float As[16][128];
    __shared__ float Bs[16][128];
    __shared__ float rowacc[128];
    const int tid = threadIdx.x;
    const int M0 = blockIdx.y * 128;
    const int N0 = blockIdx.x * 128;
    const int lr = tid >> 2;
    const int lc = (tid & 3) << 2;
    const int tx = tid & 15, ty = tid >> 4;
    float acc[8][8] = {};

    for (int k0 = 0; k0 < RANK; k0 += 16) {
#pragma unroll
        for (int r = 0; r < 2; ++r) {
            float4 a = *(const float4*)&A[(size_t)(M0 + lr + r * 64) * RANK + k0 + lc];
            As[lc + 0][lr + r * 64] = a.x; As[lc + 1][lr + r * 64] = a.y;
            As[lc + 2][lr + r * 64] = a.z; As[lc + 3][lr + r * 64] = a.w;
            float4 b = *(const float4*)&Bm[(size_t)(N0 + lr + r * 64) * RANK + k0 + lc];
            Bs[lc + 0][lr + r * 64] = b.x; Bs[lc + 1][lr + r * 64] = b.y;
            Bs[lc + 2][lr + r * 64] = b.z; Bs[lc + 3][lr + r * 64] = b.w;
        }
        __syncthreads();
#pragma unroll
        for (int k = 0; k < 16; ++k) {
            float a[8], b[8];
            *(float4*)&a[0] = *(const float4*)&As[k][ty * 8];
            *(float4*)&a[4] = *(const float4*)&As[k][ty * 8 + 4];
            *(float4*)&b[0] = *(const float4*)&Bs[k][tx * 8];
            *(float4*)&b[4] = *(const float4*)&Bs[k][tx * 8 + 4];
#pragma unroll
            for (int i = 0; i < 8; ++i)
#pragma unroll
                for (int j = 0; j < 8; ++j)
                    acc[i][j] = fmaf(a[i], b[j], acc[i][j]);
        }
        __syncthreads();
    }

    // epilogue: per-row sum of exp(10*sim)
    if (tid < 128) rowacc[tid] = 0.f;
    __syncthreads();
#pragma unroll
    for (int i = 0; i < 8; ++i) {
        float e = 0.f;
#pragma unroll
        for (int j = 0; j < 8; ++j) e += __expf(acc[i][j] * 10.f);
        atomicAdd(&rowacc[ty * 8 + i], e);
    }
    __syncthreads();
    if (tid < 128) atomicAdd(&g_sumexp[M0 + tid], rowacc[tid]);
}

__global__ __launch_bounds__(256) void final_kernel(float* __restrict__ out) {
    const int tid = threadIdx.x;
    float lacc = 0.f, pacc = 0.f, dacc = 0.f;
    for (int i = tid; i < NB; i += 256) {
        float d = g_diag[i];
        lacc += logf(g_sumexp[i]) - d * 10.f;
        pacc += d;
    }
    for (int c = tid; c < RANK; c += 256) dacc += g_colz[c] * g_colc[c];
#pragma unroll
    for (int o = 16; o; o >>= 1) {
        lacc += __shfl_xor_sync(0xffffffffu, lacc, o);
        pacc += __shfl_xor_sync(0xffffffffu, pacc, o);
        dacc += __shfl_xor_sync(0xffffffffu, dacc, o);
    }
    __shared__ float ws[3][8];
    if ((tid & 31) == 0) {
        ws[0][tid >> 5] = lacc; ws[1][tid >> 5] = pacc; ws[2][tid >> 5] = dacc;
    }
    __syncthreads();
    if (tid == 0) {
        float L = 0.f, P = 0.f, D = 0.f;
#pragma unroll
        for (int w = 0; w < 8; ++w) { L += ws[0][w]; P += ws[1][w]; D += ws[2][w]; }
        out[0] = L / (float)NB;                       // loss
        out[1] = P * 10.f / (float)NB;                // sim_pos
        out[2] = D * 10.f / ((float)NB * (float)NB);  // sim_mean
    }
}

extern "C" void kernel_launch(void* const* d_in, const int* in_sizes, int n_in,
                              void* d_out, int out_size) {
    const float* h = (const float*)d_in[0];
    const float* W = (const float*)d_in[1];
    if (in_sizes[0] == RANK * DIM) {  // defensive: swap if metadata order differs
        const float* t = h; h = W; W = t;
    }
    float* out = (float*)d_out;

    init_kernel<<<32, 256>>>();
    proj_kernel<<<dim3(4, 128), 256>>>(h, W);     // 16384x512x2048
    normalize_kernel<<<2 * NB, 128>>>();
    diag_kernel<<<NB, 128>>>();
    colsum_kernel<<<64, 256>>>();
    sim_kernel<<<dim3(64, 64), 256>>>();          // 8192x8192x512 + fused exp reduce
    final_kernel<<<1, 256>>>(out);
}

// round 3
// speedup vs baseline: 2.4364x; 2.4364x over previous
#include <cuda_runtime.h>
#include <cuda_bf16.h>
#include <math.h>
#include <stdint.h>

#define NB   8192
#define DIM  2048
#define RANK 512

// ───────── device scratch (allocation-free contract) ─────────
__device__ __align__(16) __nv_bfloat16 g_hs[(size_t)2 * NB * 2 * DIM];  // [16384][4096] = [hi | lo]
__device__ __align__(16) __nv_bfloat16 g_Ws[(size_t)RANK * 2 * DIM];    // [512][4096]  = [hi | lo]
__device__ float g_P[(size_t)2 * NB * RANK];                            // fp32 projections
__device__ __align__(16) __nv_bfloat16 g_Pb[(size_t)2 * NB * RANK];     // bf16 normalized projections
__device__ float g_sumexp[NB];
__device__ float g_diag[NB];
__device__ float g_colz[RANK];
__device__ float g_colc[RANK];

// ───────── PTX helpers (plain sm_103-legal: cp.async / ldmatrix / mma.sync) ─────────
__device__ __forceinline__ uint32_t s2u(const void* p) {
    uint32_t a;
    asm("{ .reg .u64 t; cvta.to.shared.u64 t, %1; cvt.u32.u64 %0, t; }" : "=r"(a) : "l"(p));
    return a;
}
#define CPCG(dst, src) asm volatile("cp.async.cg.shared.global [%0], [%1], 16;" :: "r"(dst), "l"(src))
#define CPCOMMIT()     asm volatile("cp.async.commit_group;")
#define CPWAIT1()      asm volatile("cp.async.wait_group 1;")
#define LDSM4(r0, r1, r2, r3, a) \
    asm volatile("ldmatrix.sync.aligned.m8n8.x4.shared.b16 {%0,%1,%2,%3}, [%4];" \
                 : "=r"(r0), "=r"(r1), "=r"(r2), "=r"(r3) : "r"(a))
#define MMA16816(d, a, b0, b1) \
    asm volatile("mma.sync.aligned.m16n8k16.row.col.f32.bf16.bf16.f32 " \
                 "{%0,%1,%2,%3}, {%4,%5,%6,%7}, {%8,%9}, {%0,%1,%2,%3};" \
                 : "+f"((d)[0]), "+f"((d)[1]), "+f"((d)[2]), "+f"((d)[3]) \
                 : "r"((a)[0]), "r"((a)[1]), "r"((a)[2]), "r"((a)[3]), "r"(b0), "r"(b1))

#define STAGES 3
#define STG_BYTES 32768   // A 16KB + B 16KB per stage (128 rows x 64 bf16 each)

// ───────── small kernels ─────────
__global__ void init_kernel() {
    int i = blockIdx.x * blockDim.x + threadIdx.x;
    if (i < NB) g_sumexp[i] = 0.f;
    if (i < RANK) { g_colz[i] = 0.f; g_colc[i] = 0.f; }
}

// fp32 -> concatenated [hi | lo] bf16 rows
__device__ __forceinline__ void split4(const float4 v, uint2& uh, uint2& ul) {
    __nv_bfloat16 h0 = __float2bfloat16_rn(v.x), h1 = __float2bfloat16_rn(v.y);
    __nv_bfloat16 h2 = __float2bfloat16_rn(v.z), h3 = __float2bfloat16_rn(v.w);
    __nv_bfloat16 l0 = __float2bfloat16_rn(v.x - __bfloat162float(h0));
    __nv_bfloat16 l1 = __float2bfloat16_rn(v.y - __bfloat162float(h1));
    __nv_bfloat16 l2 = __float2bfloat16_rn(v.z - __bfloat162float(h2));
    __nv_bfloat16 l3 = __float2bfloat16_rn(v.w - __bfloat162float(h3));
    __nv_bfloat162 ph0 = __halves2bfloat162(h0, h1), ph1 = __halves2bfloat162(h2, h3);
    __nv_bfloat162 pl0 = __halves2bfloat162(l0, l1), pl1 = __halves2bfloat162(l2, l3);
    uh.x = *(uint32_t*)&ph0; uh.y = *(uint32_t*)&ph1;
    ul.x = *(uint32_t*)&pl0; ul.y = *(uint32_t*)&pl1;
}
__global__ __launch_bounds__(256) void cvt_h_kernel(const float4* __restrict__ src) {
    const size_t n4 = (size_t)2 * NB * DIM / 4;
    for (size_t i = (size_t)blockIdx.x * 256 + threadIdx.x; i < n4; i += (size_t)gridDim.x * 256) {
        float4 v = src[i];
        size_t row = i >> 9;           // / (2048/4)
        int c4 = (int)(i & 511);
        uint2 uh, ul; split4(v, uh, ul);
        *(uint2*)&g_hs[row * 4096 + c4 * 4] = uh;
        *(uint2*)&g_hs[row * 4096 + 2048 + c4 * 4] = ul;
    }
}
__global__ __launch_bounds__(256) void cvt_w_kernel(const float4* __restrict__ src) {
    const size_t n4 = (size_t)RANK * DIM / 4;
    for (size_t i = (size_t)blockIdx.x * 256 + threadIdx.x; i < n4; i += (size_t)gridDim.x * 256) {
        float4 v = src[i];
        size_t row = i >> 9;
        int c4 = (int)(i & 511);
        uint2 uh, ul; split4(v, uh, ul);
        *(uint2*)&g_Ws[row * 4096 + c4 * 4] = uh;
        *(uint2*)&g_Ws[row * 4096 + 2048 + c4 * 4] = ul;
    }
}

// ───────── proj GEMM: P = h @ W^T, split-bf16 over 96 virtual K-chunks ─────────
// chunks 0..31: hi*hi, 32..63: hi*lo, 64..95: lo*hi
__global__ void __launch_bounds__(256, 2) proj_mma_kernel() {
    extern __shared__ char smc[];
    const uint32_t sbase = s2u(smc) + 1024;
    const int tid = threadIdx.x, wid = tid >> 5, lane = tid & 31;
    const int M0 = blockIdx.y * 128, N0 = blockIdx.x * 128;
    const int wm = wid >> 2, wn = wid & 3;          // warp m64 x n32

    // cp.async mapping: thread -> (row, 4 units of 16B)
    const int ldr = tid >> 1;
    const int ldu = (tid & 1) * 4;
    const char* gA = (const char*)(g_hs + (size_t)(M0 + ldr) * (2 * DIM));
    const char* gB = (const char*)(g_Ws + (size_t)(N0 + ldr) * (2 * DIM));
    uint32_t stA[4];
#pragma unroll
    for (int j = 0; j < 4; ++j)
        stA[j] = (uint32_t)((ldr * 8 + ((ldu + j) ^ (ldr & 7))) * 16);

    // ldmatrix lane geometry
    const int tle = lane >> 3, tr = lane & 7;
    int rA[4], rB[2];
#pragma unroll
    for (int mf = 0; mf < 4; ++mf) rA[mf] = wm * 64 + mf * 16 + (tle & 1) * 8 + tr;
#pragma unroll
    for (int nf2 = 0; nf2 < 2; ++nf2) rB[nf2] = wn * 32 + nf2 * 16 + ((tle >> 1) & 1) * 8 + tr;
    const int kuA = tle >> 1, kuB = tle & 1;

    float acc[4][4][4] = {};

#define PROJ_LOAD(c, s) do { \
        int cc = (c) & 31; \
        int ka = ((c) < 64 ? cc * 64 : 2048 + cc * 64); \
        int kb = ((c) < 32 ? cc * 64 : ((c) < 64 ? 2048 + cc * 64 : cc * 64)); \
        const char* pa = gA + ka * 2; \
        const char* pb = gB + kb * 2; \
        uint32_t bb = sbase + (s) * STG_BYTES; \
        for (int j = 0; j < 4; ++j) { \
            CPCG(bb + stA[j], pa + (ldu + j) * 16); \
            CPCG(bb + 16384 + stA[j], pb + (ldu + j) * 16); \
        } \
        CPCOMMIT(); \
    } while (0)

    PROJ_LOAD(0, 0);
    PROJ_LOAD(1, 1);

    const int C = 96;
    for (int c = 0; c < C; ++c) {
        CPWAIT1();
        __syncthreads();
        const int s = c % STAGES;
        if (c + 2 < C) PROJ_LOAD(c + 2, (c + 2) % STAGES); else CPCOMMIT();
        const uint32_t aS = sbase + s * STG_BYTES;
        const uint32_t bS = aS + 16384;
#pragma unroll
        for (int ks = 0; ks < 4; ++ks) {
            uint32_t af[4][4], bf[2][4];
#pragma unroll
            for (int mf = 0; mf < 4; ++mf) {
                uint32_t ad = aS + (uint32_t)((rA[mf] * 8 + ((ks * 2 + kuA) ^ (rA[mf] & 7))) * 16);
                LDSM4(af[mf][0], af[mf][1], af[mf][2], af[mf][3], ad);
            }
#pragma unroll
            for (int nf2 = 0; nf2 < 2; ++nf2) {
                uint32_t bd = bS + (uint32_t)((rB[nf2] * 8 + ((ks * 2 + kuB) ^ (rB[nf2] & 7))) * 16);
                LDSM4(bf[nf2][0], bf[nf2][1], bf[nf2][2], bf[nf2][3], bd);
            }
#pragma unroll
            for (int mf = 0; mf < 4; ++mf)
#pragma unroll
                for (int nf = 0; nf < 4; ++nf) {
                    const int h = nf >> 1, o = (nf & 1) * 2;
                    MMA16816(acc[mf][nf], af[mf], bf[h][o], bf[h][o + 1]);
                }
        }
    }

    // epilogue: fp32 stores to g_P
    const int gidr = lane >> 2, tig = lane & 3;
#pragma unroll
    for (int mf = 0; mf < 4; ++mf)
#pragma unroll
        for (int nf = 0; nf < 4; ++nf) {
            int row = M0 + wm * 64 + mf * 16 + gidr;
            int col = N0 + wn * 32 + nf * 8 + tig * 2;
            float2 v0 = make_float2(acc[mf][nf][0], acc[mf][nf][1]);
            float2 v1 = make_float2(acc[mf][nf][2], acc[mf][nf][3]);
            *(float2*)&g_P[(size_t)row * RANK + col] = v0;
            *(float2*)&g_P[(size_t)(row + 8) * RANK + col] = v1;
        }
#undef PROJ_LOAD
}

// ───────── normalize rows of P -> fp32 in place + bf16 copy ─────────
__global__ __launch_bounds__(128) void normalize_kernel() {
    const int row = blockIdx.x;
    const int tid = threadIdx.x;
    float4 v = *(float4*)&g_P[(size_t)row * RANK + tid * 4];
    float ss = v.x * v.x + v.y * v.y + v.z * v.z + v.w * v.w;
#pragma unroll
    for (int o = 16; o; o >>= 1) ss += __shfl_xor_sync(0xffffffffu, ss, o);
    __shared__ float ws[4];
    if ((tid & 31) == 0) ws[tid >> 5] = ss;
    __syncthreads();
    float inv = rsqrtf(ws[0] + ws[1] + ws[2] + ws[3]);
    v.x *= inv; v.y *= inv; v.z *= inv; v.w *= inv;
    *(float4*)&g_P[(size_t)row * RANK + tid * 4] = v;
    __nv_bfloat162 p0 = __floats2bfloat162_rn(v.x, v.y);
    __nv_bfloat162 p1 = __floats2bfloat162_rn(v.z, v.w);
    uint2 u; u.x = *(uint32_t*)&p0; u.y = *(uint32_t*)&p1;
    *(uint2*)&g_Pb[(size_t)row * RANK + tid * 4] = u;
}

__global__ __launch_bounds__(128) void diag_kernel() {
    const int i = blockIdx.x;
    const int tid = threadIdx.x;
    float4 z = *(const float4*)&g_P[(size_t)i * RANK + tid * 4];
    float4 c = *(const float4*)&g_P[(size_t)(i + NB) * RANK + tid * 4];
    float d = z.x * c.x + z.y * c.y + z.z * c.z + z.w * c.w;
#pragma unroll
    for (int o = 16; o; o >>= 1) d += __shfl_xor_sync(0xffffffffu, d, o);
    __shared__ float ws[4];
    if ((tid & 31) == 0) ws[tid >> 5] = d;
    __syncthreads();
    if (tid == 0) g_diag[i] = ws[0] + ws[1] + ws[2] + ws[3];
}

__global__ __launch_bounds__(256) void colsum_kernel() {
    const int rb = blockIdx.x * 128;
    const int t = threadIdx.x;
    float z0 = 0.f, z1 = 0.f, c0 = 0.f, c1 = 0.f;
    for (int r = 0; r < 128; ++r) {
        const float* pz = &g_P[(size_t)(rb + r) * RANK];
        const float* pc = &g_P[(size_t)(rb + r + NB) * RANK];
        z0 += pz[t]; z1 += pz[t + 256];
        c0 += pc[t]; c1 += pc[t + 256];
    }
    atomicAdd(&g_colz[t], z0); atomicAdd(&g_colz[t + 256], z1);
    atomicAdd(&g_colc[t], c0); atomicAdd(&g_colc[t + 256], c1);
}

// ───────── sim GEMM: Zhat @ Chat^T (bf16) + fused exp row-reduce ─────────
__global__ void __launch_bounds__(256, 2) sim_mma_kernel() {
    extern __shared__ char smc[];
    float* rowacc = (float*)smc;
    const uint32_t sbase = s2u(smc) + 1024;
    const int tid = threadIdx.x, wid = tid >> 5, lane = tid & 31;
    const int M0 = blockIdx.y * 128, N0 = blockIdx.x * 128;
    const int wm = wid >> 2, wn = wid & 3;

    const int ldr = tid >> 1;
    const int ldu = (tid & 1) * 4;
    const char* gA = (const char*)(g_Pb + (size_t)(M0 + ldr) * RANK);
    const char* gB = (const char*)(g_Pb + (size_t)(NB + N0 + ldr) * RANK);
    uint32_t stA[4];
#pragma unroll
    for (int j = 0; j < 4; ++j)
        stA[j] = (uint32_t)((ldr * 8 + ((ldu + j) ^ (ldr & 7))) * 16);

    const int tle = lane >> 3, tr = lane & 7;
    int rA[4], rB[2];
#pragma unroll
    for (int mf = 0; mf < 4; ++mf) rA[mf] = wm * 64 + mf * 16 + (tle & 1) * 8 + tr;
#pragma unroll
    for (int nf2 = 0; nf2 < 2; ++nf2) rB[nf2] = wn * 32 + nf2 * 16 + ((tle >> 1) & 1) * 8 + tr;
    const int kuA = tle >> 1, kuB = tle & 1;

    if (tid < 128) rowacc[tid] = 0.f;

    float acc[4][4][4] = {};

#define SIM_LOAD(c, s) do { \
        const char* pa = gA + (c) * 128; \
        const char* pb = gB + (c) * 128; \
        uint32_t bb = sbase + (s) * STG_BYTES; \
        for (int j = 0; j < 4; ++j) { \
            CPCG(bb + stA[j], pa + (ldu + j) * 16); \
            CPCG(bb + 16384 + stA[j], pb + (ldu + j) * 16); \
        } \
        CPCOMMIT(); \
    } while (0)

    SIM_LOAD(0, 0);
    SIM_LOAD(1, 1);

    const int C = RANK / 64;  // 8
    for (int c = 0; c < C; ++c) {
        CPWAIT1();
        __syncthreads();
        const int s = c % STAGES;
        if (c + 2 < C) SIM_LOAD(c + 2, (c + 2) % STAGES); else CPCOMMIT();
        const uint32_t aS = sbase + s * STG_BYTES;
        const uint32_t bS = aS + 16384;
#pragma unroll
        for (int ks = 0; ks < 4; ++ks) {
            uint32_t af[4][4], bf[2][4];
#pragma unroll
            for (int mf = 0; mf < 4; ++mf) {
                uint32_t ad = aS + (uint32_t)((rA[mf] * 8 + ((ks * 2 + kuA) ^ (rA[mf] & 7))) * 16);
                LDSM4(af[mf][0], af[mf][1], af[mf][2], af[mf][3], ad);
            }
#pragma unroll
            for (int nf2 = 0; nf2 < 2; ++nf2) {
                uint32_t bd = bS + (uint32_t)((rB[nf2] * 8 + ((ks * 2 + kuB) ^ (rB[nf2] & 7))) * 16);
                LDSM4(bf[nf2][0], bf[nf2][1], bf[nf2][2], bf[nf2][3], bd);
            }
#pragma unroll
            for (int mf = 0; mf < 4; ++mf)
#pragma unroll
                for (int nf = 0; nf < 4; ++nf) {
                    const int h = nf >> 1, o = (nf & 1) * 2;
                    MMA16816(acc[mf][nf], af[mf], bf[h][o], bf[h][o + 1]);
                }
        }
    }

    // epilogue: row sums of exp(10*sim)
    __syncthreads();
    const int gidr = lane >> 2, tig = lane & 3;
#pragma unroll
    for (int mf = 0; mf < 4; ++mf) {
        float s0 = 0.f, s1 = 0.f;
#pragma unroll
        for (int nf = 0; nf < 4; ++nf) {
            s0 += __expf(acc[mf][nf][0] * 10.f) + __expf(acc[mf][nf][1] * 10.f);
            s1 += __expf(acc[mf][nf][2] * 10.f) + __expf(acc[mf][nf][3] * 10.f);
        }
        s0 += __shfl_xor_sync(0xffffffffu, s0, 1);
        s0 += __shfl_xor_sync(0xffffffffu, s0, 2);
        s1 += __shfl_xor_sync(0xffffffffu, s1, 1);
        s1 += __shfl_xor_sync(0xffffffffu, s1, 2);
        if (tig == 0) {
            atomicAdd(&rowacc[wm * 64 + mf * 16 + gidr], s0);
            atomicAdd(&rowacc[wm * 64 + mf * 16 + gidr + 8], s1);
        }
    }
    __syncthreads();
    if (tid < 128) atomicAdd(&g_sumexp[M0 + tid], rowacc[tid]);
#undef SIM_LOAD
}

// ───────── final reduction ─────────
__global__ __launch_bounds__(256) void final_kernel(float* __restrict__ out) {
    const int tid = threadIdx.x;
    float lacc = 0.f, pacc = 0.f, dacc = 0.f;
    for (int i = tid; i < NB; i += 256) {
        float d = g_diag[i];
        lacc += logf(g_sumexp[i]) - d * 10.f;
        pacc += d;
    }
    for (int c = tid; c < RANK; c += 256) dacc += g_colz[c] * g_colc[c];
#pragma unroll
    for (int o = 16; o; o >>= 1) {
        lacc += __shfl_xor_sync(0xffffffffu, lacc, o);
        pacc += __shfl_xor_sync(0xffffffffu, pacc, o);
        dacc += __shfl_xor_sync(0xffffffffu, dacc, o);
    }
    __shared__ float ws[3][8];
    if ((tid & 31) == 0) { ws[0][tid >> 5] = lacc; ws[1][tid >> 5] = pacc; ws[2][tid >> 5] = dacc; }
    __syncthreads();
    if (tid == 0) {
        float L = 0.f, P = 0.f, D = 0.f;
#pragma unroll
        for (int w = 0; w < 8; ++w) { L += ws[0][w]; P += ws[1][w]; D += ws[2][w]; }
        out[0] = L / (float)NB;
        out[1] = P * 10.f / (float)NB;
        out[2] = D * 10.f / ((float)NB * (float)NB);
    }
}

// ───────── launch ─────────
#define GEMM_SMEM (1024 + STAGES * STG_BYTES)

extern "C" void kernel_launch(void* const* d_in, const int* in_sizes, int n_in,
                              void* d_out, int out_size) {
    const float* h = (const float*)d_in[0];
    const float* W = (const float*)d_in[1];
    if (in_sizes[0] == RANK * DIM) { const float* t = h; h = W; W = t; }
    float* out = (float*)d_out;

    cudaFuncSetAttribute(proj_mma_kernel, cudaFuncAttributeMaxDynamicSharedMemorySize, GEMM_SMEM);
    cudaFuncSetAttribute(sim_mma_kernel, cudaFuncAttributeMaxDynamicSharedMemorySize, GEMM_SMEM);

    init_kernel<<<32, 256>>>();
    cvt_h_kernel<<<1024, 256>>>((const float4*)h);
    cvt_w_kernel<<<128, 256>>>((const float4*)W);
    proj_mma_kernel<<<dim3(4, 128), 256, GEMM_SMEM>>>();
    normalize_kernel<<<2 * NB, 128>>>();
    diag_kernel<<<NB, 128>>>();
    colsum_kernel<<<64, 256>>>();
    sim_mma_kernel<<<dim3(64, 64), 256, GEMM_SMEM>>>();
    final_kernel<<<1, 256>>>(out);
}

// round 4
// speedup vs baseline: 5.9358x; 2.4363x over previous
#include <cuda_runtime.h>
#include <cuda_bf16.h>
#include <math.h>
#include <stdint.h>

#define NB   8192
#define DIM  2048
#define RANK 512

// ───────── device scratch (allocation-free contract) ─────────
__device__ __align__(16) __nv_bfloat16 g_hs[(size_t)2 * NB * DIM];   // bf16(h)
__device__ __align__(16) __nv_bfloat16 g_Ws[(size_t)RANK * DIM];     // bf16(W)
__device__ float g_P[(size_t)2 * NB * RANK];                         // fp32 projections
__device__ __align__(16) __nv_bfloat16 g_Pb[(size_t)2 * NB * RANK];  // bf16 normalized projections
__device__ float g_sumexp[NB];
__device__ float g_diag[NB];
__device__ float g_colz[RANK];
__device__ float g_colc[RANK];

// ───────── PTX helpers (plain sm_103-legal: cp.async / ldmatrix / mma.sync) ─────────
__device__ __forceinline__ uint32_t s2u(const void* p) {
    uint32_t a;
    asm("{ .reg .u64 t; cvta.to.shared.u64 t, %1; cvt.u32.u64 %0, t; }" : "=r"(a) : "l"(p));
    return a;
}
#define CPCG(dst, src) asm volatile("cp.async.cg.shared.global [%0], [%1], 16;" :: "r"(dst), "l"(src))
#define CPCOMMIT()     asm volatile("cp.async.commit_group;")
#define CPWAIT1()      asm volatile("cp.async.wait_group 1;")
#define LDSM4(r0, r1, r2, r3, a) \
    asm volatile("ldmatrix.sync.aligned.m8n8.x4.shared.b16 {%0,%1,%2,%3}, [%4];" \
                 : "=r"(r0), "=r"(r1), "=r"(r2), "=r"(r3) : "r"(a))
#define MMA16816(d, a, b0, b1) \
    asm volatile("mma.sync.aligned.m16n8k16.row.col.f32.bf16.bf16.f32 " \
                 "{%0,%1,%2,%3}, {%4,%5,%6,%7}, {%8,%9}, {%0,%1,%2,%3};" \
                 : "+f"((d)[0]), "+f"((d)[1]), "+f"((d)[2]), "+f"((d)[3]) \
                 : "r"((a)[0]), "r"((a)[1]), "r"((a)[2]), "r"((a)[3]), "r"(b0), "r"(b1))

#define STAGES 3
#define STG_BYTES 32768   // A 16KB + B 16KB per stage (128 rows x 64 bf16 each)

// ───────── small kernels ─────────
__global__ void init_kernel() {
    int i = blockIdx.x * blockDim.x + threadIdx.x;
    if (i < NB) g_sumexp[i] = 0.f;
    if (i < RANK) { g_colz[i] = 0.f; g_colc[i] = 0.f; }
}

__device__ __forceinline__ uint2 pack4(const float4 v) {
    __nv_bfloat162 p0 = __floats2bfloat162_rn(v.x, v.y);
    __nv_bfloat162 p1 = __floats2bfloat162_rn(v.z, v.w);
    uint2 u; u.x = *(uint32_t*)&p0; u.y = *(uint32_t*)&p1;
    return u;
}
__global__ __launch_bounds__(256) void cvt_h_kernel(const float4* __restrict__ src) {
    const size_t n4 = (size_t)2 * NB * DIM / 4;
    for (size_t i = (size_t)blockIdx.x * 256 + threadIdx.x; i < n4; i += (size_t)gridDim.x * 256)
        *(uint2*)&g_hs[i * 4] = pack4(src[i]);
}
__global__ __launch_bounds__(256) void cvt_w_kernel(const float4* __restrict__ src) {
    const size_t n4 = (size_t)RANK * DIM / 4;
    for (size_t i = (size_t)blockIdx.x * 256 + threadIdx.x; i < n4; i += (size_t)gridDim.x * 256)
        *(uint2*)&g_Ws[i * 4] = pack4(src[i]);
}

// ───────── proj GEMM: P = h @ W^T (plain bf16, K=2048 in 32 chunks of 64) ─────────
__global__ void __launch_bounds__(256, 2) proj_mma_kernel() {
    extern __shared__ char smc[];
    const uint32_t sbase = s2u(smc) + 1024;
    const int tid = threadIdx.x, wid = tid >> 5, lane = tid & 31;
    const int M0 = blockIdx.y * 128, N0 = blockIdx.x * 128;
    const int wm = wid >> 2, wn = wid & 3;          // warp m64 x n32

    const int ldr = tid >> 1;
    const int ldu = (tid & 1) * 4;
    const char* gA = (const char*)(g_hs + (size_t)(M0 + ldr) * DIM);
    const char* gB = (const char*)(g_Ws + (size_t)(N0 + ldr) * DIM);
    uint32_t stA[4];
#pragma unroll
    for (int j = 0; j < 4; ++j)
        stA[j] = (uint32_t)((ldr * 8 + ((ldu + j) ^ (ldr & 7))) * 16);

    const int tle = lane >> 3, tr = lane & 7;
    int rA[4], rB[2];
#pragma unroll
    for (int mf = 0; mf < 4; ++mf) rA[mf] = wm * 64 + mf * 16 + (tle & 1) * 8 + tr;
#pragma unroll
    for (int nf2 = 0; nf2 < 2; ++nf2) rB[nf2] = wn * 32 + nf2 * 16 + ((tle >> 1) & 1) * 8 + tr;
    const int kuA = tle >> 1, kuB = tle & 1;

    float acc[4][4][4] = {};

#define PROJ_LOAD(c, s) do { \
        const char* pa = gA + (size_t)(c) * 128; \
        const char* pb = gB + (size_t)(c) * 128; \
        uint32_t bb = sbase + (s) * STG_BYTES; \
        for (int j = 0; j < 4; ++j) { \
            CPCG(bb + stA[j], pa + (ldu + j) * 16); \
            CPCG(bb + 16384 + stA[j], pb + (ldu + j) * 16); \
        } \
        CPCOMMIT(); \
    } while (0)

    PROJ_LOAD(0, 0);
    PROJ_LOAD(1, 1);

    const int C = DIM / 64;  // 32
    for (int c = 0; c < C; ++c) {
        CPWAIT1();
        __syncthreads();
        const int s = c % STAGES;
        if (c + 2 < C) PROJ_LOAD(c + 2, (c + 2) % STAGES); else CPCOMMIT();
        const uint32_t aS = sbase + s * STG_BYTES;
        const uint32_t bS = aS + 16384;
#pragma unroll
        for (int ks = 0; ks < 4; ++ks) {
            uint32_t af[4][4], bf[2][4];
#pragma unroll
            for (int mf = 0; mf < 4; ++mf) {
                uint32_t ad = aS + (uint32_t)((rA[mf] * 8 + ((ks * 2 + kuA) ^ (rA[mf] & 7))) * 16);
                LDSM4(af[mf][0], af[mf][1], af[mf][2], af[mf][3], ad);
            }
#pragma unroll
            for (int nf2 = 0; nf2 < 2; ++nf2) {
                uint32_t bd = bS + (uint32_t)((rB[nf2] * 8 + ((ks * 2 + kuB) ^ (rB[nf2] & 7))) * 16);
                LDSM4(bf[nf2][0], bf[nf2][1], bf[nf2][2], bf[nf2][3], bd);
            }
#pragma unroll
            for (int mf = 0; mf < 4; ++mf)
#pragma unroll
                for (int nf = 0; nf < 4; ++nf) {
                    const int h = nf >> 1, o = (nf & 1) * 2;
                    MMA16816(acc[mf][nf], af[mf], bf[h][o], bf[h][o + 1]);
                }
        }
    }

    const int gidr = lane >> 2, tig = lane & 3;
#pragma unroll
    for (int mf = 0; mf < 4; ++mf)
#pragma unroll
        for (int nf = 0; nf < 4; ++nf) {
            int row = M0 + wm * 64 + mf * 16 + gidr;
            int col = N0 + wn * 32 + nf * 8 + tig * 2;
            float2 v0 = make_float2(acc[mf][nf][0], acc[mf][nf][1]);
            float2 v1 = make_float2(acc[mf][nf][2], acc[mf][nf][3]);
            *(float2*)&g_P[(size_t)row * RANK + col] = v0;
            *(float2*)&g_P[(size_t)(row + 8) * RANK + col] = v1;
        }
#undef PROJ_LOAD
}

// ───────── normalize rows of P -> fp32 in place + bf16 copy ─────────
__global__ __launch_bounds__(128) void normalize_kernel() {
    const int row = blockIdx.x;
    const int tid = threadIdx.x;
    float4 v = *(float4*)&g_P[(size_t)row * RANK + tid * 4];
    float ss = v.x * v.x + v.y * v.y + v.z * v.z + v.w * v.w;
#pragma unroll
    for (int o = 16; o; o >>= 1) ss += __shfl_xor_sync(0xffffffffu, ss, o);
    __shared__ float ws[4];
    if ((tid & 31) == 0) ws[tid >> 5] = ss;
    __syncthreads();
    float inv = rsqrtf(ws[0] + ws[1] + ws[2] + ws[3]);
    v.x *= inv; v.y *= inv; v.z *= inv; v.w *= inv;
    *(float4*)&g_P[(size_t)row * RANK + tid * 4] = v;
    *(uint2*)&g_Pb[(size_t)row * RANK + tid * 4] = pack4(v);
}

__global__ __launch_bounds__(128) void diag_kernel() {
    const int i = blockIdx.x;
    const int tid = threadIdx.x;
    float4 z = *(const float4*)&g_P[(size_t)i * RANK + tid * 4];
    float4 c = *(const float4*)&g_P[(size_t)(i + NB) * RANK + tid * 4];
    float d = z.x * c.x + z.y * c.y + z.z * c.z + z.w * c.w;
#pragma unroll
    for (int o = 16; o; o >>= 1) d += __shfl_xor_sync(0xffffffffu, d, o);
    __shared__ float ws[4];
    if ((tid & 31) == 0) ws[tid >> 5] = d;
    __syncthreads();
    if (tid == 0) g_diag[i] = ws[0] + ws[1] + ws[2] + ws[3];
}

__global__ __launch_bounds__(256) void colsum_kernel() {
    const int rb = blockIdx.x * 128;
    const int t = threadIdx.x;
    float z0 = 0.f, z1 = 0.f, c0 = 0.f, c1 = 0.f;
    for (int r = 0; r < 128; ++r) {
        const float* pz = &g_P[(size_t)(rb + r) * RANK];
        const float* pc = &g_P[(size_t)(rb + r + NB) * RANK];
        z0 += pz[t]; z1 += pz[t + 256];
        c0 += pc[t]; c1 += pc[t + 256];
    }
    atomicAdd(&g_colz[t], z0); atomicAdd(&g_colz[t + 256], z1);
    atomicAdd(&g_colc[t], c0); atomicAdd(&g_colc[t + 256], c1);
}

// ───────── sim GEMM: Zhat @ Chat^T (bf16) + fused exp row-reduce ─────────
__global__ void __launch_bounds__(256, 2) sim_mma_kernel() {
    extern __shared__ char smc[];
    float* rowacc = (float*)smc;
    const uint32_t sbase = s2u(smc) + 1024;
    const int tid = threadIdx.x, wid = tid >> 5, lane = tid & 31;
    const int M0 = blockIdx.y * 128, N0 = blockIdx.x * 128;
    const int wm = wid >> 2, wn = wid & 3;

    const int ldr = tid >> 1;
    const int ldu = (tid & 1) * 4;
    const char* gA = (const char*)(g_Pb + (size_t)(M0 + ldr) * RANK);
    const char* gB = (const char*)(g_Pb + (size_t)(NB + N0 + ldr) * RANK);
    uint32_t stA[4];
#pragma unroll
    for (int j = 0; j < 4; ++j)
        stA[j] = (uint32_t)((ldr * 8 + ((ldu + j) ^ (ldr & 7))) * 16);

    const int tle = lane >> 3, tr = lane & 7;
    int rA[4], rB[2];
#pragma unroll
    for (int mf = 0; mf < 4; ++mf) rA[mf] = wm * 64 + mf * 16 + (tle & 1) * 8 + tr;
#pragma unroll
    for (int nf2 = 0; nf2 < 2; ++nf2) rB[nf2] = wn * 32 + nf2 * 16 + ((tle >> 1) & 1) * 8 + tr;
    const int kuA = tle >> 1, kuB = tle & 1;

    if (tid < 128) rowacc[tid] = 0.f;

    float acc[4][4][4] = {};

#define SIM_LOAD(c, s) do { \
        const char* pa = gA + (c) * 128; \
        const char* pb = gB + (c) * 128; \
        uint32_t bb = sbase + (s) * STG_BYTES; \
        for (int j = 0; j < 4; ++j) { \
            CPCG(bb + stA[j], pa + (ldu + j) * 16); \
            CPCG(bb + 16384 + stA[j], pb + (ldu + j) * 16); \
        } \
        CPCOMMIT(); \
    } while (0)

    SIM_LOAD(0, 0);
    SIM_LOAD(1, 1);

    const int C = RANK / 64;  // 8
    for (int c = 0; c < C; ++c) {
        CPWAIT1();
        __syncthreads();
        const int s = c % STAGES;
        if (c + 2 < C) SIM_LOAD(c + 2, (c + 2) % STAGES); else CPCOMMIT();
        const uint32_t aS = sbase + s * STG_BYTES;
        const uint32_t bS = aS + 16384;
#pragma unroll
        for (int ks = 0; ks < 4; ++ks) {
            uint32_t af[4][4], bf[2][4];
#pragma unroll
            for (int mf = 0; mf < 4; ++mf) {
                uint32_t ad = aS + (uint32_t)((rA[mf] * 8 + ((ks * 2 + kuA) ^ (rA[mf] & 7))) * 16);
                LDSM4(af[mf][0], af[mf][1], af[mf][2], af[mf][3], ad);
            }
#pragma unroll
            for (int nf2 = 0; nf2 < 2; ++nf2) {
                uint32_t bd = bS + (uint32_t)((rB[nf2] * 8 + ((ks * 2 + kuB) ^ (rB[nf2] & 7))) * 16);
                LDSM4(bf[nf2][0], bf[nf2][1], bf[nf2][2], bf[nf2][3], bd);
            }
#pragma unroll
            for (int mf = 0; mf < 4; ++mf)
#pragma unroll
                for (int nf = 0; nf < 4; ++nf) {
                    const int h = nf >> 1, o = (nf & 1) * 2;
                    MMA16816(acc[mf][nf], af[mf], bf[h][o], bf[h][o + 1]);
                }
        }
    }

    __syncthreads();
    const int gidr = lane >> 2, tig = lane & 3;
#pragma unroll
    for (int mf = 0; mf < 4; ++mf) {
        float s0 = 0.f, s1 = 0.f;
#pragma unroll
        for (int nf = 0; nf < 4; ++nf) {
            s0 += __expf(acc[mf][nf][0] * 10.f) + __expf(acc[mf][nf][1] * 10.f);
            s1 += __expf(acc[mf][nf][2] * 10.f) + __expf(acc[mf][nf][3] * 10.f);
        }
        s0 += __shfl_xor_sync(0xffffffffu, s0, 1);
        s0 += __shfl_xor_sync(0xffffffffu, s0, 2);
        s1 += __shfl_xor_sync(0xffffffffu, s1, 1);
        s1 += __shfl_xor_sync(0xffffffffu, s1, 2);
        if (tig == 0) {
            atomicAdd(&rowacc[wm * 64 + mf * 16 + gidr], s0);
            atomicAdd(&rowacc[wm * 64 + mf * 16 + gidr + 8], s1);
        }
    }
    __syncthreads();
    if (tid < 128) atomicAdd(&g_sumexp[M0 + tid], rowacc[tid]);
#undef SIM_LOAD
}

// ───────── final reduction ─────────
__global__ __launch_bounds__(256) void final_kernel(float* __restrict__ out) {
    const int tid = threadIdx.x;
    float lacc = 0.f, pacc = 0.f, dacc = 0.f;
    for (int i = tid; i < NB; i += 256) {
        float d = g_diag[i];
        lacc += logf(g_sumexp[i]) - d * 10.f;
        pacc += d;
    }
    for (int c = tid; c < RANK; c += 256) dacc += g_colz[c] * g_colc[c];
#pragma unroll
    for (int o = 16; o; o >>= 1) {
        lacc += __shfl_xor_sync(0xffffffffu, lacc, o);
        pacc += __shfl_xor_sync(0xffffffffu, pacc, o);
        dacc += __shfl_xor_sync(0xffffffffu, dacc, o);
    }
    __shared__ float ws[3][8];
    if ((tid & 31) == 0) { ws[0][tid >> 5] = lacc; ws[1][tid >> 5] = pacc; ws[2][tid >> 5] = dacc; }
    __syncthreads();
    if (tid == 0) {
        float L = 0.f, P = 0.f, D = 0.f;
#pragma unroll
        for (int w = 0; w < 8; ++w) { L += ws[0][w]; P += ws[1][w]; D += ws[2][w]; }
        out[0] = L / (float)NB;
        out[1] = P * 10.f / (float)NB;
        out[2] = D * 10.f / ((float)NB * (float)NB);
    }
}

// ───────── launch ─────────
#define GEMM_SMEM (1024 + STAGES * STG_BYTES)

extern "C" void kernel_launch(void* const* d_in, const int* in_sizes, int n_in,
                              void* d_out, int out_size) {
    const float* h = (const float*)d_in[0];
    const float* W = (const float*)d_in[1];
    if (in_sizes[0] == RANK * DIM) { const float* t = h; h = W; W = t; }
    float* out = (float*)d_out;

    cudaFuncSetAttribute(proj_mma_kernel, cudaFuncAttributeMaxDynamicSharedMemorySize, GEMM_SMEM);
    cudaFuncSetAttribute(sim_mma_kernel, cudaFuncAttributeMaxDynamicSharedMemorySize, GEMM_SMEM);

    init_kernel<<<32, 256>>>();
    cvt_h_kernel<<<1024, 256>>>((const float4*)h);
    cvt_w_kernel<<<128, 256>>>((const float4*)W);
    proj_mma_kernel<<<dim3(4, 128), 256, GEMM_SMEM>>>();
    normalize_kernel<<<2 * NB, 128>>>();
    diag_kernel<<<NB, 128>>>();
    colsum_kernel<<<64, 256>>>();
    sim_mma_kernel<<<dim3(64, 64), 256, GEMM_SMEM>>>();
    final_kernel<<<1, 256>>>(out);
}